// round 6
// baseline (speedup 1.0000x reference)
#include <cuda_runtime.h>
#include <math.h>
#include <stdint.h>

#define BB 2
#define NN 4
#define CCH 128
#define HEADS 8
#define PP 4
#define HH 96
#define WW 96
#define TCC 64
#define NITERS 3
#define HD 16
#define HWSZ (HH*WW)   // 9216

// ---------------- scratch (device globals; no allocation) ----------------
__device__ float g_q   [BB*CCH*HWSZ];          // BCHW
__device__ float g_v   [BB*NN*CCH*HWSZ];       // BCHW
__device__ float g_tmp [BB*CCH*HWSZ];          // BCHW
__device__ float g_net [BB*HEADS*HWSZ*HD];     // pixel-head-major
__device__ float g_agg [BB*CCH*HWSZ];          // BCHW
__device__ float g_ent [BB*HEADS*HWSZ];
__device__ float g_tbias[BB*HEADS*NN];
__device__ int   g_nid [BB];
__device__ float g_wprep[5*8*4096];            // pre-split/permuted conv weights
__device__ float g_sw  [BB*HEADS*HWSZ*16];     // softmax weights
__device__ float g_off [BB*HEADS*HWSZ*8];      // final offsets

__device__ __forceinline__ float geluf(float v){ return 0.5f*v*(1.0f+erff(v*0.70710678118654752f)); }
__device__ __forceinline__ float sigm(float v){ return 1.0f/(1.0f+expf(-v)); }
__device__ __forceinline__ float tf32r(float x){
    uint32_t o; asm("cvt.rna.tf32.f32 %0, %1;" : "=r"(o) : "f"(x));
    return __uint_as_float(o);
}
__device__ __forceinline__ void mma8(float* c, const float* a, const float* b){
    asm volatile("mma.sync.aligned.m16n8k8.row.col.f32.tf32.tf32.f32 "
        "{%0,%1,%2,%3}, {%4,%5,%6,%7}, {%8,%9}, {%0,%1,%2,%3};"
        : "+f"(c[0]),"+f"(c[1]),"+f"(c[2]),"+f"(c[3])
        : "r"(__float_as_uint(a[0])),"r"(__float_as_uint(a[1])),
          "r"(__float_as_uint(a[2])),"r"(__float_as_uint(a[3])),
          "r"(__float_as_uint(b[0])),"r"(__float_as_uint(b[1])));
}

// ---------------- weight prep: permute + hi/lo split, once ----------------
__global__ void wprep_k(const float* __restrict__ qw, const float* __restrict__ vw,
                        const float* __restrict__ pww, const float* __restrict__ o1w,
                        const float* __restrict__ o2w)
{
    const float* ws[5] = {qw, vw, pww, o1w, o2w};
    int ck = blockIdx.x;            // k-chunk 0..7
    int ci = blockIdx.y;            // conv id 0..4
    const float* w = ws[ci];
    int tid = threadIdx.x;
    int oc  = tid >> 1;
    int klb = (tid & 1) * 8;
    const float* wp = w + (size_t)oc * CCH + ck*16 + klb;
    float4 v0 = *reinterpret_cast<const float4*>(wp);
    float4 v1 = *reinterpret_cast<const float4*>(wp + 4);
    float vv[8] = {v0.x,v0.y,v0.z,v0.w,v1.x,v1.y,v1.z,v1.w};
    int mt = oc >> 4, og = oc & 15, gi = og & 7, half = og >> 3;
    float* dst = g_wprep + ((size_t)ci*8 + ck)*4096;
    #pragma unroll
    for (int j=0;j<8;j++){
        int kl = klb + j;
        int kc = kl >> 3, kk = kl & 7;
        int tt = kk & 3, khalf = kk >> 2;
        int idx = ((mt*2+kc)*32 + gi*4 + tt)*4 + (half + 2*khalf);
        float hi = tf32r(vv[j]);
        dst[idx]        = hi;
        dst[2048 + idx] = tf32r(vv[j] - hi);
    }
}

// ---------------- tiny kernel: t_bias + nearest_idx ----------------
__global__ void small_k(const float* __restrict__ rel_time,
                        const float* __restrict__ time_enc,
                        const float* __restrict__ tw,
                        const float* __restrict__ tb)
{
    int t = threadIdx.x;
    if (t < BB*HEADS*NN) {
        int n = t % NN; int h = (t/NN) % HEADS; int b = t/(NN*HEADS);
        float s = tb[h];
        for (int k=0;k<TCC;k++) s += time_enc[(b*NN+n)*TCC+k]*tw[h*TCC+k];
        g_tbias[t] = s;
    } else if (t < BB*HEADS*NN + BB) {
        int b = t - BB*HEADS*NN;
        float best = fabsf(rel_time[b*NN]); int id = 0;
        for (int n=1;n<NN;n++){ float v=fabsf(rel_time[b*NN+n]); if (v<best){best=v;id=n;} }
        g_nid[b] = id;
    }
}

// ---------------- depthwise 7x7 + bias + gelu (smem tiled) ----------------
__global__ __launch_bounds__(256)
void dw_k(const float* __restrict__ q,
          const float* __restrict__ dww,
          const float* __restrict__ dwb)
{
    __shared__ float tile[38][40];
    __shared__ float wsm[49];
    int plane = blockIdx.z;            // b*CCH + c
    int c = plane & (CCH-1);
    int tx0 = blockIdx.x * 32;
    int ty0 = blockIdx.y * 32;
    const float* qp = q + (size_t)plane * HWSZ;
    int tid = threadIdx.x;
    if (tid < 49) wsm[tid] = dww[c*49 + tid];
    for (int i = tid; i < 38*38; i += 256){
        int r = i / 38, cc = i - r*38;
        int gy = ty0 + r - 3, gx = tx0 + cc - 3;
        float v = 0.f;
        if (gy>=0 && gy<HH && gx>=0 && gx<WW) v = qp[gy*WW+gx];
        tile[r][cc] = v;
    }
    __syncthreads();
    float wr[49];
    #pragma unroll
    for (int i=0;i<49;i++) wr[i]=wsm[i];
    int lx = tid & 31;
    int ly0 = tid >> 5;
    float bz = dwb[c];
    float* outp = g_tmp + (size_t)plane*HWSZ;
    #pragma unroll
    for (int j=0;j<4;j++){
        int ly = ly0 + j*8;
        float acc = 0.f;
        #pragma unroll
        for (int ky=0;ky<7;ky++)
            #pragma unroll
            for (int kx=0;kx<7;kx++)
                acc += tile[ly+ky][lx+kx]*wr[ky*7+kx];
        outp[(ty0+ly)*WW + tx0+lx] = geluf(acc + bz);
    }
}

// ---------------- 3xTF32 tensor-core conv1x1 (fp32-accurate) ----------------
// C[oc][pix] = sum_k W[oc][k] * in[k][pix] + bias[oc]
// act: 0 none, 1 gelu, 2 *sigmoid(gate[oc]).  layout: 0 BCHW out, 1 pixel-head-major out
__global__ __launch_bounds__(256)
void conv1x1_mma_k(const float* __restrict__ in, const float* __restrict__ wA,
                   const float* __restrict__ bias, float* __restrict__ out,
                   int act, int layout, const float* __restrict__ gate)
{
    __shared__ float sA[4096];           // [hi2048 | lo2048] permuted W chunk
    __shared__ float sB[2][16*132];      // hi/lo [k16][pix128 + pad4]
    const int tid  = threadIdx.x;
    const int lane = tid & 31;
    const int warp = tid >> 5;
    const int g  = lane >> 2;
    const int t4 = lane & 3;

    const int pix0 = blockIdx.x * 128;
    const int img  = blockIdx.y;
    const float* inb = in + (size_t)img * CCH * HWSZ;

    const int wOc  = (warp & 1) * 64;
    const int wPix = (warp >> 1) * 32;

    float c[4][4][4];
    #pragma unroll
    for (int i=0;i<4;i++)
        #pragma unroll
        for (int j=0;j<4;j++)
            #pragma unroll
            for (int r=0;r<4;r++) c[i][j][r]=0.f;

    for (int k0 = 0; k0 < CCH; k0 += 16) {
        // stage prepped W chunk: pure copy
        {
            const float4* src = reinterpret_cast<const float4*>(wA + (size_t)(k0>>4)*4096);
            float4* dA = reinterpret_cast<float4*>(sA);
            dA[tid]       = src[tid];
            dA[tid + 256] = src[tid + 256];
            dA[tid + 512] = src[tid + 512];
            dA[tid + 768] = src[tid + 768];
        }
        // stage input chunk, hi + lo
        {
            int kl = tid >> 4;
            int px = (tid & 15) * 8;
            const float* ip = inb + (size_t)(k0+kl)*HWSZ + pix0 + px;
            float4 v0 = *reinterpret_cast<const float4*>(ip);
            float4 v1 = *reinterpret_cast<const float4*>(ip+4);
            float vv[8] = {v0.x,v0.y,v0.z,v0.w,v1.x,v1.y,v1.z,v1.w};
            int base = kl*132 + px;
            #pragma unroll
            for (int j=0;j<8;j++){
                float hi = tf32r(vv[j]);
                sB[0][base+j] = hi;
                sB[1][base+j] = tf32r(vv[j] - hi);
            }
        }
        __syncthreads();
        #pragma unroll
        for (int kc=0; kc<2; kc++){
            float ah[4][4], al[4][4];
            #pragma unroll
            for (int mt=0; mt<4; mt++){
                int mtg = (wOc>>4) + mt;
                int idx = ((mtg*2+kc)*32+lane)*4;
                float4 avh = *reinterpret_cast<const float4*>(&sA[idx]);
                float4 avl = *reinterpret_cast<const float4*>(&sA[2048+idx]);
                ah[mt][0]=avh.x; ah[mt][1]=avh.y; ah[mt][2]=avh.z; ah[mt][3]=avh.w;
                al[mt][0]=avl.x; al[mt][1]=avl.y; al[mt][2]=avl.z; al[mt][3]=avl.w;
            }
            float bh[4][2], bl[4][2];
            #pragma unroll
            for (int nt=0; nt<4; nt++){
                int px = wPix + nt*8 + g;
                int i0 = (kc*8+t4)*132 + px;
                int i1 = (kc*8+t4+4)*132 + px;
                bh[nt][0] = sB[0][i0];  bh[nt][1] = sB[0][i1];
                bl[nt][0] = sB[1][i0];  bl[nt][1] = sB[1][i1];
            }
            #pragma unroll
            for (int mt=0; mt<4; mt++)
                #pragma unroll
                for (int nt=0; nt<4; nt++){
                    mma8(c[mt][nt], ah[mt], bl[nt]);
                    mma8(c[mt][nt], al[mt], bh[nt]);
                    mma8(c[mt][nt], ah[mt], bh[nt]);
                }
        }
        __syncthreads();
    }

    // epilogue
    #pragma unroll
    for (int mt=0; mt<4; mt++){
        int oc1 = wOc + mt*16 + g;
        int oc2 = oc1 + 8;
        float b1 = bias[oc1], b2 = bias[oc2];
        float m1 = 1.f, m2 = 1.f;
        if (act==2){ m1 = sigm(gate[oc1]); m2 = sigm(gate[oc2]); }
        #pragma unroll
        for (int nt=0; nt<4; nt++){
            int p = pix0 + wPix + nt*8 + t4*2;
            float v0 = c[mt][nt][0] + b1, v1 = c[mt][nt][1] + b1;
            float v2 = c[mt][nt][2] + b2, v3 = c[mt][nt][3] + b2;
            if (act==1){ v0=geluf(v0); v1=geluf(v1); v2=geluf(v2); v3=geluf(v3); }
            else if (act==2){ v0*=m1; v1*=m1; v2*=m2; v3*=m2; }
            if (layout==0){
                float2* o1 = reinterpret_cast<float2*>(out + (size_t)img*CCH*HWSZ + (size_t)oc1*HWSZ + p);
                float2* o2 = reinterpret_cast<float2*>(out + (size_t)img*CCH*HWSZ + (size_t)oc2*HWSZ + p);
                *o1 = make_float2(v0, v1);
                *o2 = make_float2(v2, v3);
            } else {
                out[(((size_t)img*HEADS + (oc1>>4))*HWSZ + p  )*HD + (oc1&15)] = v0;
                out[(((size_t)img*HEADS + (oc1>>4))*HWSZ + p+1)*HD + (oc1&15)] = v1;
                out[(((size_t)img*HEADS + (oc2>>4))*HWSZ + p  )*HD + (oc2&15)] = v2;
                out[(((size_t)img*HEADS + (oc2>>4))*HWSZ + p+1)*HD + (oc2&15)] = v3;
            }
        }
    }
}

// ---------------- fused: correlation + GRU iters + softmax (no gather) ----------------
__global__ __launch_bounds__(128)
void fused_k(const float* __restrict__ wih, const float* __restrict__ whh,
             const float* __restrict__ bih, const float* __restrict__ bhh,
             const float* __restrict__ offw, const float* __restrict__ offb,
             const float* __restrict__ aw,  const float* __restrict__ ab)
{
    __shared__ float s_wih[48*18];
    __shared__ float s_whh[48*16];
    __shared__ float s_misc[48+48+8+4];
    __shared__ float s_offw[8*16];
    __shared__ float s_aw[4*16];

    int t = threadIdx.x;
    for (int i=t;i<48*18;i+=128) s_wih[i]=wih[i];
    for (int i=t;i<48*16;i+=128) s_whh[i]=whh[i];
    if (t<48)            s_misc[t]      = bih[t];
    else if (t<96)       s_misc[t]      = bhh[t-48];
    else if (t<104)      s_misc[t]      = offb[t-96];
    else if (t<108)      s_misc[t]      = ab[t-104];
    s_offw[t] = offw[t];
    if (t<64) s_aw[t] = aw[t];
    __syncthreads();
    const float* s_bih = s_misc;
    const float* s_bhh = s_misc+48;
    const float* s_offb= s_misc+96;
    const float* s_ab  = s_misc+104;

    int ph  = blockIdx.x*128 + t;
    int pix = ph % HWSZ;
    int bh  = ph / HWSZ;
    int h   = bh % HEADS;
    int b   = bh / HEADS;
    int x   = pix % WW, y = pix / WW;
    float bx = -1.f + x*(2.f/(WW-1));
    float by = -1.f + y*(2.f/(HH-1));

    const float* vnear = g_v + ((size_t)(b*NN + g_nid[b])*CCH + h*HD)*HWSZ;
    const float* qbase = g_q + ((size_t)b*CCH + h*HD)*HWSZ + pix;

    float qv[HD];
    #pragma unroll
    for (int d=0;d<HD;d++) qv[d] = qbase[(size_t)d*HWSZ];
    const int sdx[5] = {0,-1,1,0,0};
    const int sdy[5] = {0,0,0,-1,1};
    float bestsc = 0.f; int bi = 0;
    #pragma unroll
    for (int s=0;s<5;s++){
        int sy = y - sdy[s], sx = x - sdx[s];
        float sc = 0.f;
        if (sy>=0 && sy<HH && sx>=0 && sx<WW){
            int sp = sy*WW+sx;
            #pragma unroll
            for (int d=0;d<HD;d++) sc += qv[d]*vnear[(size_t)d*HWSZ + sp];
        }
        if (s==0 || sc > bestsc){ bestsc = sc; bi = s; }
    }
    float ox0 = sdy[bi]*(2.f/WW);
    float oy0 = sdx[bi]*(2.f/HH);

    float offs[PP*2];
    #pragma unroll
    for (int p=0;p<PP;p++){ offs[2*p]=ox0; offs[2*p+1]=oy0; }
    float attn[PP] = {0.f,0.f,0.f,0.f};

    float net[HD];
    const float* np_ = g_net + (size_t)ph*HD;
    #pragma unroll
    for (int d=0;d<HD;d++) net[d] = np_[d];

    for (int it=0; it<NITERS; it++){
        float p0x = offs[0], p0y = offs[1];
        float sgx = fminf(fmaxf(bx+p0x,-1.f),1.f);
        float sgy = fminf(fmaxf(by+p0y,-1.f),1.f);
        float ixf = (sgx+1.f)*0.5f*(WW-1);
        float iyf = (sgy+1.f)*0.5f*(HH-1);
        float x0f = floorf(ixf), y0f = floorf(iyf);
        float wx = ixf-x0f, wy = iyf-y0f;
        int x0 = min(max((int)x0f,0),WW-1);
        int x1 = min(max((int)x0f+1,0),WW-1);
        int y0 = min(max((int)y0f,0),HH-1);
        int y1 = min(max((int)y0f+1,0),HH-1);
        int i00=y0*WW+x0, i01=y0*WW+x1, i10=y1*WW+x0, i11=y1*WW+x1;
        float w00=(1.f-wx)*(1.f-wy), w01=wx*(1.f-wy), w10=(1.f-wx)*wy, w11=wx*wy;

        float xin[HD+2];
        #pragma unroll
        for (int d=0;d<HD;d++){
            const float* pl = vnear + (size_t)d*HWSZ;
            xin[d] = pl[i00]*w00 + pl[i01]*w01 + pl[i10]*w10 + pl[i11]*w11;
        }
        xin[HD]=p0x; xin[HD+1]=p0y;

        float r[HD], z[HD], hn[HD];
        for (int j=0;j<HD;j++){
            float gi = s_bih[j], gh = s_bhh[j];
            #pragma unroll
            for (int k=0;k<HD+2;k++) gi += xin[k]*s_wih[j*(HD+2)+k];
            #pragma unroll
            for (int k=0;k<HD;k++)   gh += net[k]*s_whh[j*HD+k];
            r[j] = sigm(gi+gh);
        }
        for (int j=0;j<HD;j++){
            float gi = s_bih[HD+j], gh = s_bhh[HD+j];
            #pragma unroll
            for (int k=0;k<HD+2;k++) gi += xin[k]*s_wih[(HD+j)*(HD+2)+k];
            #pragma unroll
            for (int k=0;k<HD;k++)   gh += net[k]*s_whh[(HD+j)*HD+k];
            z[j] = sigm(gi+gh);
        }
        for (int j=0;j<HD;j++){
            float gi = s_bih[2*HD+j], gh = s_bhh[2*HD+j];
            #pragma unroll
            for (int k=0;k<HD+2;k++) gi += xin[k]*s_wih[(2*HD+j)*(HD+2)+k];
            #pragma unroll
            for (int k=0;k<HD;k++)   gh += net[k]*s_whh[(2*HD+j)*HD+k];
            hn[j] = tanhf(gi + r[j]*gh);
        }
        for (int j=0;j<HD;j++) net[j] = (1.f-z[j])*hn[j] + z[j]*net[j];

        #pragma unroll
        for (int p=0;p<PP;p++){
            float d0 = s_offb[2*p], d1 = s_offb[2*p+1], da = s_ab[p];
            #pragma unroll
            for (int d=0;d<HD;d++){
                d0 += net[d]*s_offw[(2*p)*HD+d];
                d1 += net[d]*s_offw[(2*p+1)*HD+d];
                da += net[d]*s_aw[p*HD+d];
            }
            offs[2*p]+=d0; offs[2*p+1]+=d1; attn[p]+=da;
        }
    }

    float lg[NN*PP];
    float m = -1e30f;
    #pragma unroll
    for (int n=0;n<NN;n++){
        float tbv = g_tbias[bh*NN+n];
        #pragma unroll
        for (int p=0;p<PP;p++){ float v2 = attn[p]+tbv; lg[n*PP+p]=v2; m = fmaxf(m,v2); }
    }
    float ssum = 0.f;
    #pragma unroll
    for (int i=0;i<NN*PP;i++){ lg[i]=expf(lg[i]-m); ssum += lg[i]; }
    float inv = 1.f/ssum;
    float ent = 0.f;
    #pragma unroll
    for (int i=0;i<NN*PP;i++){ lg[i]*=inv; ent -= lg[i]*logf(lg[i]+1e-8f); }
    g_ent[(size_t)bh*HWSZ + pix] = ent;

    // write softmax weights + offsets
    float4* swp = reinterpret_cast<float4*>(g_sw + (size_t)ph*16);
    #pragma unroll
    for (int i=0;i<4;i++)
        swp[i] = make_float4(lg[4*i], lg[4*i+1], lg[4*i+2], lg[4*i+3]);
    float4* ofp = reinterpret_cast<float4*>(g_off + (size_t)ph*8);
    ofp[0] = make_float4(offs[0], offs[1], offs[2], offs[3]);
    ofp[1] = make_float4(offs[4], offs[5], offs[6], offs[7]);
}

// ---------------- final gather: 4 threads per pixel-head (one per frame n) ----------------
__global__ __launch_bounds__(256)
void gather_k()
{
    int tid = threadIdx.x;
    int phl = tid >> 2;
    int n   = tid & 3;
    int ph  = blockIdx.x*64 + phl;
    int pix = ph % HWSZ;
    int bh  = ph / HWSZ;
    int h   = bh % HEADS;
    int b   = bh / HEADS;
    int x   = pix % WW, y = pix / WW;
    float bx = -1.f + x*(2.f/(WW-1));
    float by = -1.f + y*(2.f/(HH-1));

    const float4* ofp = reinterpret_cast<const float4*>(g_off + (size_t)ph*8);
    float4 o0 = ofp[0], o1 = ofp[1];
    float offs[8] = {o0.x,o0.y,o0.z,o0.w,o1.x,o1.y,o1.z,o1.w};
    const float* swp = g_sw + (size_t)ph*16;
    const float* vb2 = g_v + ((size_t)(b*NN+n)*CCH + h*HD)*HWSZ;

    float acc[HD];
    #pragma unroll
    for (int d=0;d<HD;d++) acc[d]=0.f;

    #pragma unroll
    for (int p=0;p<PP;p++){
        float sgx = fminf(fmaxf(bx+offs[2*p],-1.f),1.f);
        float sgy = fminf(fmaxf(by+offs[2*p+1],-1.f),1.f);
        float ixf = (sgx+1.f)*0.5f*(WW-1);
        float iyf = (sgy+1.f)*0.5f*(HH-1);
        float x0f = floorf(ixf), y0f = floorf(iyf);
        float wx = ixf-x0f, wy = iyf-y0f;
        int x0 = min(max((int)x0f,0),WW-1);
        int x1 = min(max((int)x0f+1,0),WW-1);
        int y0 = min(max((int)y0f,0),HH-1);
        int y1 = min(max((int)y0f+1,0),HH-1);
        int i00=y0*WW+x0, i01=y0*WW+x1, i10=y1*WW+x0, i11=y1*WW+x1;
        float w00=(1.f-wx)*(1.f-wy), w01=wx*(1.f-wy), w10=(1.f-wx)*wy, w11=wx*wy;
        float wnp = swp[n*PP+p];
        #pragma unroll
        for (int d=0;d<HD;d++){
            const float* pl = vb2 + (size_t)d*HWSZ;
            acc[d] += wnp*(pl[i00]*w00 + pl[i01]*w01 + pl[i10]*w10 + pl[i11]*w11);
        }
    }

    // reduce over n (4 consecutive lanes)
    #pragma unroll
    for (int d=0;d<HD;d++){
        acc[d] += __shfl_xor_sync(0xffffffffu, acc[d], 1);
        acc[d] += __shfl_xor_sync(0xffffffffu, acc[d], 2);
    }
    if (n == 0){
        float* op = g_agg + ((size_t)b*CCH + h*HD)*HWSZ + pix;
        #pragma unroll
        for (int d=0;d<HD;d++) op[(size_t)d*HWSZ] = acc[d];
    }
}

// ---------------- entropy mean + confidence ----------------
__global__ void ent_k(float* __restrict__ out)
{
    int i = blockIdx.x*blockDim.x + threadIdx.x;
    if (i >= BB*HWSZ) return;
    int b = i / HWSZ, pix = i % HWSZ;
    float s = 0.f;
    #pragma unroll
    for (int h=0;h<HEADS;h++) s += g_ent[(size_t)(b*HEADS+h)*HWSZ + pix];
    s *= (1.0f/HEADS);
    float conf = 1.f - fminf(fmaxf(s/(2.7725887222397811f+1e-8f),0.f),1.f);
    out[(size_t)BB*CCH*HWSZ + i] = conf;
    out[(size_t)BB*CCH*HWSZ + BB*HWSZ + i] = s;
}

// ---------------- launch ----------------
extern "C" void kernel_launch(void* const* d_in, const int* in_sizes, int n_in,
                              void* d_out, int out_size)
{
    const float* query    = (const float*)d_in[0];
    const float* values   = (const float*)d_in[1];
    const float* rel_time = (const float*)d_in[2];
    const float* time_enc = (const float*)d_in[3];
    const float* qw  = (const float*)d_in[4];
    const float* qb  = (const float*)d_in[5];
    const float* vw  = (const float*)d_in[6];
    const float* vb  = (const float*)d_in[7];
    const float* dww = (const float*)d_in[8];
    const float* dwb = (const float*)d_in[9];
    const float* pww = (const float*)d_in[10];
    const float* pwb = (const float*)d_in[11];
    const float* wih = (const float*)d_in[12];
    const float* whh = (const float*)d_in[13];
    const float* bih = (const float*)d_in[14];
    const float* bhh = (const float*)d_in[15];
    const float* offw= (const float*)d_in[16];
    const float* offb= (const float*)d_in[17];
    const float* aw  = (const float*)d_in[18];
    const float* ab  = (const float*)d_in[19];
    const float* tw  = (const float*)d_in[20];
    const float* tb  = (const float*)d_in[21];
    const float* o1w = (const float*)d_in[22];
    const float* o1b = (const float*)d_in[23];
    const float* o2w = (const float*)d_in[24];
    const float* o2b = (const float*)d_in[25];
    const float* gate= (const float*)d_in[26];
    float* out = (float*)d_out;

    float *p_q, *p_v, *p_tmp, *p_net, *p_agg, *p_wprep;
    cudaGetSymbolAddress((void**)&p_q,    g_q);
    cudaGetSymbolAddress((void**)&p_v,    g_v);
    cudaGetSymbolAddress((void**)&p_tmp,  g_tmp);
    cudaGetSymbolAddress((void**)&p_net,  g_net);
    cudaGetSymbolAddress((void**)&p_agg,  g_agg);
    cudaGetSymbolAddress((void**)&p_wprep,g_wprep);

    small_k<<<1,128>>>(rel_time, time_enc, tw, tb);
    wprep_k<<<dim3(8,5),256>>>(qw, vw, pww, o1w, o2w);
    conv1x1_mma_k<<<dim3(HWSZ/128, BB),    256>>>(query,  p_wprep + 0*8*4096, qb,  p_q,   0, 0, nullptr);
    conv1x1_mma_k<<<dim3(HWSZ/128, BB*NN), 256>>>(values, p_wprep + 1*8*4096, vb,  p_v,   0, 0, nullptr);
    dw_k<<<dim3(3,3,BB*CCH), 256>>>(query, dww, dwb);
    conv1x1_mma_k<<<dim3(HWSZ/128, BB),    256>>>(p_tmp,  p_wprep + 2*8*4096, pwb, p_net, 0, 1, nullptr);
    fused_k<<<(BB*HEADS*HWSZ)/128, 128>>>(wih, whh, bih, bhh, offw, offb, aw, ab);
    gather_k<<<(BB*HEADS*HWSZ)/64, 256>>>();
    conv1x1_mma_k<<<dim3(HWSZ/128, BB),    256>>>(p_agg,  p_wprep + 3*8*4096, o1b, p_tmp, 1, 0, nullptr);
    conv1x1_mma_k<<<dim3(HWSZ/128, BB),    256>>>(p_tmp,  p_wprep + 4*8*4096, o2b, out,   2, 0, gate);
    ent_k<<<(BB*HWSZ)/128, 128>>>(out);
}

// round 7
// speedup vs baseline: 1.4909x; 1.4909x over previous
#include <cuda_runtime.h>
#include <math.h>
#include <stdint.h>

#define BB 2
#define NN 4
#define CCH 128
#define HEADS 8
#define PP 4
#define HH 96
#define WW 96
#define TCC 64
#define NITERS 3
#define HD 16
#define HWSZ (HH*WW)   // 9216

// ---------------- scratch (device globals; no allocation) ----------------
__device__ float g_q   [BB*CCH*HWSZ];          // BCHW
__device__ float g_v   [BB*NN*CCH*HWSZ];       // BCHW
__device__ float g_tmp [BB*CCH*HWSZ];          // BCHW
__device__ float g_net [BB*HEADS*HWSZ*HD];     // pixel-head-major
__device__ float g_agg [BB*CCH*HWSZ];          // BCHW
__device__ float g_ent [BB*HEADS*HWSZ];
__device__ float g_tbias[BB*HEADS*NN];
__device__ int   g_nid [BB];
__device__ float g_wprep[5*8*4096];            // pre-split/permuted conv weights

__device__ __forceinline__ float geluf(float v){ return 0.5f*v*(1.0f+erff(v*0.70710678118654752f)); }
__device__ __forceinline__ float sigm(float v){ return 1.0f/(1.0f+expf(-v)); }
__device__ __forceinline__ float tf32r(float x){
    uint32_t o; asm("cvt.rna.tf32.f32 %0, %1;" : "=r"(o) : "f"(x));
    return __uint_as_float(o);
}
__device__ __forceinline__ void mma8(float* c, const float* a, const float* b){
    asm volatile("mma.sync.aligned.m16n8k8.row.col.f32.tf32.tf32.f32 "
        "{%0,%1,%2,%3}, {%4,%5,%6,%7}, {%8,%9}, {%0,%1,%2,%3};"
        : "+f"(c[0]),"+f"(c[1]),"+f"(c[2]),"+f"(c[3])
        : "r"(__float_as_uint(a[0])),"r"(__float_as_uint(a[1])),
          "r"(__float_as_uint(a[2])),"r"(__float_as_uint(a[3])),
          "r"(__float_as_uint(b[0])),"r"(__float_as_uint(b[1])));
}

// ---------------- weight prep: permute + hi/lo split, once ----------------
__global__ void wprep_k(const float* __restrict__ qw, const float* __restrict__ vw,
                        const float* __restrict__ pww, const float* __restrict__ o1w,
                        const float* __restrict__ o2w)
{
    const float* ws[5] = {qw, vw, pww, o1w, o2w};
    int ck = blockIdx.x;            // k-chunk 0..7
    int ci = blockIdx.y;            // conv id 0..4
    const float* w = ws[ci];
    int tid = threadIdx.x;
    int oc  = tid >> 1;
    int klb = (tid & 1) * 8;
    const float* wp = w + (size_t)oc * CCH + ck*16 + klb;
    float4 v0 = *reinterpret_cast<const float4*>(wp);
    float4 v1 = *reinterpret_cast<const float4*>(wp + 4);
    float vv[8] = {v0.x,v0.y,v0.z,v0.w,v1.x,v1.y,v1.z,v1.w};
    int mt = oc >> 4, og = oc & 15, gi = og & 7, half = og >> 3;
    float* dst = g_wprep + ((size_t)ci*8 + ck)*4096;
    #pragma unroll
    for (int j=0;j<8;j++){
        int kl = klb + j;
        int kc = kl >> 3, kk = kl & 7;
        int tt = kk & 3, khalf = kk >> 2;
        int idx = ((mt*2+kc)*32 + gi*4 + tt)*4 + (half + 2*khalf);
        float hi = tf32r(vv[j]);
        dst[idx]        = hi;
        dst[2048 + idx] = tf32r(vv[j] - hi);
    }
}

// ---------------- tiny kernel: t_bias + nearest_idx ----------------
__global__ void small_k(const float* __restrict__ rel_time,
                        const float* __restrict__ time_enc,
                        const float* __restrict__ tw,
                        const float* __restrict__ tb)
{
    int t = threadIdx.x;
    if (t < BB*HEADS*NN) {
        int n = t % NN; int h = (t/NN) % HEADS; int b = t/(NN*HEADS);
        float s = tb[h];
        for (int k=0;k<TCC;k++) s += time_enc[(b*NN+n)*TCC+k]*tw[h*TCC+k];
        g_tbias[t] = s;
    } else if (t < BB*HEADS*NN + BB) {
        int b = t - BB*HEADS*NN;
        float best = fabsf(rel_time[b*NN]); int id = 0;
        for (int n=1;n<NN;n++){ float v=fabsf(rel_time[b*NN+n]); if (v<best){best=v;id=n;} }
        g_nid[b] = id;
    }
}

// ---------------- depthwise 7x7 + bias + gelu (smem tiled) ----------------
__global__ __launch_bounds__(256)
void dw_k(const float* __restrict__ q,
          const float* __restrict__ dww,
          const float* __restrict__ dwb)
{
    __shared__ float tile[38][40];
    __shared__ float wsm[49];
    int plane = blockIdx.z;            // b*CCH + c
    int c = plane & (CCH-1);
    int tx0 = blockIdx.x * 32;
    int ty0 = blockIdx.y * 32;
    const float* qp = q + (size_t)plane * HWSZ;
    int tid = threadIdx.x;
    if (tid < 49) wsm[tid] = dww[c*49 + tid];
    for (int i = tid; i < 38*38; i += 256){
        int r = i / 38, cc = i - r*38;
        int gy = ty0 + r - 3, gx = tx0 + cc - 3;
        float v = 0.f;
        if (gy>=0 && gy<HH && gx>=0 && gx<WW) v = qp[gy*WW+gx];
        tile[r][cc] = v;
    }
    __syncthreads();
    float wr[49];
    #pragma unroll
    for (int i=0;i<49;i++) wr[i]=wsm[i];
    int lx = tid & 31;
    int ly0 = tid >> 5;
    float bz = dwb[c];
    float* outp = g_tmp + (size_t)plane*HWSZ;
    #pragma unroll
    for (int j=0;j<4;j++){
        int ly = ly0 + j*8;
        float acc = 0.f;
        #pragma unroll
        for (int ky=0;ky<7;ky++)
            #pragma unroll
            for (int kx=0;kx<7;kx++)
                acc += tile[ly+ky][lx+kx]*wr[ky*7+kx];
        outp[(ty0+ly)*WW + tx0+lx] = geluf(acc + bz);
    }
}

// ---------------- 3xTF32 tensor-core conv1x1 (fp32-accurate) ----------------
// C[oc][pix] = sum_k W[oc][k] * in[k][pix] + bias[oc]
// act: 0 none, 1 gelu, 2 *sigmoid(gate[oc]).  layout: 0 BCHW out, 1 pixel-head-major out
__global__ __launch_bounds__(256, 2)
void conv1x1_mma_k(const float* __restrict__ in, const float* __restrict__ wA,
                   const float* __restrict__ bias, float* __restrict__ out,
                   int act, int layout, const float* __restrict__ gate)
{
    __shared__ float sA[4096];           // [hi2048 | lo2048] permuted W chunk
    __shared__ float sB[2][16*132];      // hi/lo [k16][pix128 + pad4]
    const int tid  = threadIdx.x;
    const int lane = tid & 31;
    const int warp = tid >> 5;
    const int g  = lane >> 2;
    const int t4 = lane & 3;

    const int pix0 = blockIdx.x * 128;
    const int img  = blockIdx.y;
    const float* inb = in + (size_t)img * CCH * HWSZ;

    const int wOc  = (warp & 1) * 64;
    const int wPix = (warp >> 1) * 32;

    float c[4][4][4];
    #pragma unroll
    for (int i=0;i<4;i++)
        #pragma unroll
        for (int j=0;j<4;j++)
            #pragma unroll
            for (int r=0;r<4;r++) c[i][j][r]=0.f;

    for (int k0 = 0; k0 < CCH; k0 += 16) {
        // stage prepped W chunk: pure copy
        {
            const float4* src = reinterpret_cast<const float4*>(wA + (size_t)(k0>>4)*4096);
            float4* dA = reinterpret_cast<float4*>(sA);
            dA[tid]       = src[tid];
            dA[tid + 256] = src[tid + 256];
            dA[tid + 512] = src[tid + 512];
            dA[tid + 768] = src[tid + 768];
        }
        // stage input chunk, hi + lo
        {
            int kl = tid >> 4;
            int px = (tid & 15) * 8;
            const float* ip = inb + (size_t)(k0+kl)*HWSZ + pix0 + px;
            float4 v0 = *reinterpret_cast<const float4*>(ip);
            float4 v1 = *reinterpret_cast<const float4*>(ip+4);
            float vv[8] = {v0.x,v0.y,v0.z,v0.w,v1.x,v1.y,v1.z,v1.w};
            int base = kl*132 + px;
            #pragma unroll
            for (int j=0;j<8;j++){
                float hi = tf32r(vv[j]);
                sB[0][base+j] = hi;
                sB[1][base+j] = tf32r(vv[j] - hi);
            }
        }
        __syncthreads();
        #pragma unroll
        for (int kc=0; kc<2; kc++){
            float ah[4][4], al[4][4];
            #pragma unroll
            for (int mt=0; mt<4; mt++){
                int mtg = (wOc>>4) + mt;
                int idx = ((mtg*2+kc)*32+lane)*4;
                float4 avh = *reinterpret_cast<const float4*>(&sA[idx]);
                float4 avl = *reinterpret_cast<const float4*>(&sA[2048+idx]);
                ah[mt][0]=avh.x; ah[mt][1]=avh.y; ah[mt][2]=avh.z; ah[mt][3]=avh.w;
                al[mt][0]=avl.x; al[mt][1]=avl.y; al[mt][2]=avl.z; al[mt][3]=avl.w;
            }
            float bh[4][2], bl[4][2];
            #pragma unroll
            for (int nt=0; nt<4; nt++){
                int px = wPix + nt*8 + g;
                int i0 = (kc*8+t4)*132 + px;
                int i1 = (kc*8+t4+4)*132 + px;
                bh[nt][0] = sB[0][i0];  bh[nt][1] = sB[0][i1];
                bl[nt][0] = sB[1][i0];  bl[nt][1] = sB[1][i1];
            }
            #pragma unroll
            for (int mt=0; mt<4; mt++)
                #pragma unroll
                for (int nt=0; nt<4; nt++){
                    mma8(c[mt][nt], ah[mt], bl[nt]);
                    mma8(c[mt][nt], al[mt], bh[nt]);
                    mma8(c[mt][nt], ah[mt], bh[nt]);
                }
        }
        __syncthreads();
    }

    // epilogue
    #pragma unroll
    for (int mt=0; mt<4; mt++){
        int oc1 = wOc + mt*16 + g;
        int oc2 = oc1 + 8;
        float b1 = bias[oc1], b2 = bias[oc2];
        float m1 = 1.f, m2 = 1.f;
        if (act==2){ m1 = sigm(gate[oc1]); m2 = sigm(gate[oc2]); }
        #pragma unroll
        for (int nt=0; nt<4; nt++){
            int p = pix0 + wPix + nt*8 + t4*2;
            float v0 = c[mt][nt][0] + b1, v1 = c[mt][nt][1] + b1;
            float v2 = c[mt][nt][2] + b2, v3 = c[mt][nt][3] + b2;
            if (act==1){ v0=geluf(v0); v1=geluf(v1); v2=geluf(v2); v3=geluf(v3); }
            else if (act==2){ v0*=m1; v1*=m1; v2*=m2; v3*=m2; }
            if (layout==0){
                float2* o1 = reinterpret_cast<float2*>(out + (size_t)img*CCH*HWSZ + (size_t)oc1*HWSZ + p);
                float2* o2 = reinterpret_cast<float2*>(out + (size_t)img*CCH*HWSZ + (size_t)oc2*HWSZ + p);
                *o1 = make_float2(v0, v1);
                *o2 = make_float2(v2, v3);
            } else {
                out[(((size_t)img*HEADS + (oc1>>4))*HWSZ + p  )*HD + (oc1&15)] = v0;
                out[(((size_t)img*HEADS + (oc1>>4))*HWSZ + p+1)*HD + (oc1&15)] = v1;
                out[(((size_t)img*HEADS + (oc2>>4))*HWSZ + p  )*HD + (oc2&15)] = v2;
                out[(((size_t)img*HEADS + (oc2>>4))*HWSZ + p+1)*HD + (oc2&15)] = v3;
            }
        }
    }
}

// ---------------- fused: correlation + GRU iters + softmax + final gather ----------------
__global__ __launch_bounds__(128)
void fused_k(const float* __restrict__ wih, const float* __restrict__ whh,
             const float* __restrict__ bih, const float* __restrict__ bhh,
             const float* __restrict__ offw, const float* __restrict__ offb,
             const float* __restrict__ aw,  const float* __restrict__ ab)
{
    __shared__ float s_wih[48*18];
    __shared__ float s_whh[48*16];
    __shared__ float s_misc[48+48+8+4];
    __shared__ float s_offw[8*16];
    __shared__ float s_aw[4*16];
    __shared__ float s_sw[16][128];

    int t = threadIdx.x;
    for (int i=t;i<48*18;i+=128) s_wih[i]=wih[i];
    for (int i=t;i<48*16;i+=128) s_whh[i]=whh[i];
    if (t<48)            s_misc[t]      = bih[t];
    else if (t<96)       s_misc[t]      = bhh[t-48];
    else if (t<104)      s_misc[t]      = offb[t-96];
    else if (t<108)      s_misc[t]      = ab[t-104];
    s_offw[t] = offw[t];
    if (t<64) s_aw[t] = aw[t];
    __syncthreads();
    const float* s_bih = s_misc;
    const float* s_bhh = s_misc+48;
    const float* s_offb= s_misc+96;
    const float* s_ab  = s_misc+104;

    int ph  = blockIdx.x*128 + t;
    int pix = ph % HWSZ;
    int bh  = ph / HWSZ;
    int h   = bh % HEADS;
    int b   = bh / HEADS;
    int x   = pix % WW, y = pix / WW;
    float bx = -1.f + x*(2.f/(WW-1));
    float by = -1.f + y*(2.f/(HH-1));

    const float* vnear = g_v + ((size_t)(b*NN + g_nid[b])*CCH + h*HD)*HWSZ;
    const float* qbase = g_q + ((size_t)b*CCH + h*HD)*HWSZ + pix;

    float qv[HD];
    #pragma unroll
    for (int d=0;d<HD;d++) qv[d] = qbase[(size_t)d*HWSZ];
    const int sdx[5] = {0,-1,1,0,0};
    const int sdy[5] = {0,0,0,-1,1};
    float bestsc = 0.f; int bi = 0;
    #pragma unroll
    for (int s=0;s<5;s++){
        int sy = y - sdy[s], sx = x - sdx[s];
        float sc = 0.f;
        if (sy>=0 && sy<HH && sx>=0 && sx<WW){
            int sp = sy*WW+sx;
            #pragma unroll
            for (int d=0;d<HD;d++) sc += qv[d]*vnear[(size_t)d*HWSZ + sp];
        }
        if (s==0 || sc > bestsc){ bestsc = sc; bi = s; }
    }
    float ox0 = sdy[bi]*(2.f/WW);
    float oy0 = sdx[bi]*(2.f/HH);

    float offs[PP*2];
    #pragma unroll
    for (int p=0;p<PP;p++){ offs[2*p]=ox0; offs[2*p+1]=oy0; }
    float attn[PP] = {0.f,0.f,0.f,0.f};

    float net[HD];
    const float* np_ = g_net + (size_t)ph*HD;
    #pragma unroll
    for (int d=0;d<HD;d++) net[d] = np_[d];

    for (int it=0; it<NITERS; it++){
        float p0x = offs[0], p0y = offs[1];
        float sgx = fminf(fmaxf(bx+p0x,-1.f),1.f);
        float sgy = fminf(fmaxf(by+p0y,-1.f),1.f);
        float ixf = (sgx+1.f)*0.5f*(WW-1);
        float iyf = (sgy+1.f)*0.5f*(HH-1);
        float x0f = floorf(ixf), y0f = floorf(iyf);
        float wx = ixf-x0f, wy = iyf-y0f;
        int x0 = min(max((int)x0f,0),WW-1);
        int x1 = min(max((int)x0f+1,0),WW-1);
        int y0 = min(max((int)y0f,0),HH-1);
        int y1 = min(max((int)y0f+1,0),HH-1);
        int i00=y0*WW+x0, i01=y0*WW+x1, i10=y1*WW+x0, i11=y1*WW+x1;
        float w00=(1.f-wx)*(1.f-wy), w01=wx*(1.f-wy), w10=(1.f-wx)*wy, w11=wx*wy;

        float xin[HD+2];
        #pragma unroll
        for (int d=0;d<HD;d++){
            const float* pl = vnear + (size_t)d*HWSZ;
            xin[d] = pl[i00]*w00 + pl[i01]*w01 + pl[i10]*w10 + pl[i11]*w11;
        }
        xin[HD]=p0x; xin[HD+1]=p0y;

        float r[HD], z[HD], hn[HD];
        for (int j=0;j<HD;j++){
            float gi = s_bih[j], gh = s_bhh[j];
            #pragma unroll
            for (int k=0;k<HD+2;k++) gi += xin[k]*s_wih[j*(HD+2)+k];
            #pragma unroll
            for (int k=0;k<HD;k++)   gh += net[k]*s_whh[j*HD+k];
            r[j] = sigm(gi+gh);
        }
        for (int j=0;j<HD;j++){
            float gi = s_bih[HD+j], gh = s_bhh[HD+j];
            #pragma unroll
            for (int k=0;k<HD+2;k++) gi += xin[k]*s_wih[(HD+j)*(HD+2)+k];
            #pragma unroll
            for (int k=0;k<HD;k++)   gh += net[k]*s_whh[(HD+j)*HD+k];
            z[j] = sigm(gi+gh);
        }
        for (int j=0;j<HD;j++){
            float gi = s_bih[2*HD+j], gh = s_bhh[2*HD+j];
            #pragma unroll
            for (int k=0;k<HD+2;k++) gi += xin[k]*s_wih[(2*HD+j)*(HD+2)+k];
            #pragma unroll
            for (int k=0;k<HD;k++)   gh += net[k]*s_whh[(2*HD+j)*HD+k];
            hn[j] = tanhf(gi + r[j]*gh);
        }
        for (int j=0;j<HD;j++) net[j] = (1.f-z[j])*hn[j] + z[j]*net[j];

        #pragma unroll
        for (int p=0;p<PP;p++){
            float d0 = s_offb[2*p], d1 = s_offb[2*p+1], da = s_ab[p];
            #pragma unroll
            for (int d=0;d<HD;d++){
                d0 += net[d]*s_offw[(2*p)*HD+d];
                d1 += net[d]*s_offw[(2*p+1)*HD+d];
                da += net[d]*s_aw[p*HD+d];
            }
            offs[2*p]+=d0; offs[2*p+1]+=d1; attn[p]+=da;
        }
    }

    float lg[NN*PP];
    float m = -1e30f;
    #pragma unroll
    for (int n=0;n<NN;n++){
        float tbv = g_tbias[bh*NN+n];
        #pragma unroll
        for (int p=0;p<PP;p++){ float v2 = attn[p]+tbv; lg[n*PP+p]=v2; m = fmaxf(m,v2); }
    }
    float ssum = 0.f;
    #pragma unroll
    for (int i=0;i<NN*PP;i++){ lg[i]=expf(lg[i]-m); ssum += lg[i]; }
    float inv = 1.f/ssum;
    float ent = 0.f;
    #pragma unroll
    for (int i=0;i<NN*PP;i++){ lg[i]*=inv; ent -= lg[i]*logf(lg[i]+1e-8f); s_sw[i][t]=lg[i]; }
    g_ent[(size_t)bh*HWSZ + pix] = ent;

    float acc[HD];
    #pragma unroll
    for (int d=0;d<HD;d++) acc[d]=0.f;
    #pragma unroll
    for (int p=0;p<PP;p++){
        float sgx = fminf(fmaxf(bx+offs[2*p],-1.f),1.f);
        float sgy = fminf(fmaxf(by+offs[2*p+1],-1.f),1.f);
        float ixf = (sgx+1.f)*0.5f*(WW-1);
        float iyf = (sgy+1.f)*0.5f*(HH-1);
        float x0f = floorf(ixf), y0f = floorf(iyf);
        float wx = ixf-x0f, wy = iyf-y0f;
        int x0 = min(max((int)x0f,0),WW-1);
        int x1 = min(max((int)x0f+1,0),WW-1);
        int y0 = min(max((int)y0f,0),HH-1);
        int y1 = min(max((int)y0f+1,0),HH-1);
        int i00=y0*WW+x0, i01=y0*WW+x1, i10=y1*WW+x0, i11=y1*WW+x1;
        float w00=(1.f-wx)*(1.f-wy), w01=wx*(1.f-wy), w10=(1.f-wx)*wy, w11=wx*wy;
        for (int n=0;n<NN;n++){
            float wnp = s_sw[n*PP+p][t];
            const float* vb2 = g_v + ((size_t)(b*NN+n)*CCH + h*HD)*HWSZ;
            #pragma unroll
            for (int d=0;d<HD;d++){
                const float* pl = vb2 + (size_t)d*HWSZ;
                acc[d] += wnp*(pl[i00]*w00 + pl[i01]*w01 + pl[i10]*w10 + pl[i11]*w11);
            }
        }
    }
    float* op = g_agg + ((size_t)b*CCH + h*HD)*HWSZ + pix;
    #pragma unroll
    for (int d=0;d<HD;d++) op[(size_t)d*HWSZ] = acc[d];
}

// ---------------- entropy mean + confidence ----------------
__global__ void ent_k(float* __restrict__ out)
{
    int i = blockIdx.x*blockDim.x + threadIdx.x;
    if (i >= BB*HWSZ) return;
    int b = i / HWSZ, pix = i % HWSZ;
    float s = 0.f;
    #pragma unroll
    for (int h=0;h<HEADS;h++) s += g_ent[(size_t)(b*HEADS+h)*HWSZ + pix];
    s *= (1.0f/HEADS);
    float conf = 1.f - fminf(fmaxf(s/(2.7725887222397811f+1e-8f),0.f),1.f);
    out[(size_t)BB*CCH*HWSZ + i] = conf;
    out[(size_t)BB*CCH*HWSZ + BB*HWSZ + i] = s;
}

// ---------------- launch ----------------
extern "C" void kernel_launch(void* const* d_in, const int* in_sizes, int n_in,
                              void* d_out, int out_size)
{
    const float* query    = (const float*)d_in[0];
    const float* values   = (const float*)d_in[1];
    const float* rel_time = (const float*)d_in[2];
    const float* time_enc = (const float*)d_in[3];
    const float* qw  = (const float*)d_in[4];
    const float* qb  = (const float*)d_in[5];
    const float* vw  = (const float*)d_in[6];
    const float* vb  = (const float*)d_in[7];
    const float* dww = (const float*)d_in[8];
    const float* dwb = (const float*)d_in[9];
    const float* pww = (const float*)d_in[10];
    const float* pwb = (const float*)d_in[11];
    const float* wih = (const float*)d_in[12];
    const float* whh = (const float*)d_in[13];
    const float* bih = (const float*)d_in[14];
    const float* bhh = (const float*)d_in[15];
    const float* offw= (const float*)d_in[16];
    const float* offb= (const float*)d_in[17];
    const float* aw  = (const float*)d_in[18];
    const float* ab  = (const float*)d_in[19];
    const float* tw  = (const float*)d_in[20];
    const float* tb  = (const float*)d_in[21];
    const float* o1w = (const float*)d_in[22];
    const float* o1b = (const float*)d_in[23];
    const float* o2w = (const float*)d_in[24];
    const float* o2b = (const float*)d_in[25];
    const float* gate= (const float*)d_in[26];
    float* out = (float*)d_out;

    float *p_q, *p_v, *p_tmp, *p_net, *p_agg, *p_wprep;
    cudaGetSymbolAddress((void**)&p_q,    g_q);
    cudaGetSymbolAddress((void**)&p_v,    g_v);
    cudaGetSymbolAddress((void**)&p_tmp,  g_tmp);
    cudaGetSymbolAddress((void**)&p_net,  g_net);
    cudaGetSymbolAddress((void**)&p_agg,  g_agg);
    cudaGetSymbolAddress((void**)&p_wprep,g_wprep);

    small_k<<<1,128>>>(rel_time, time_enc, tw, tb);
    wprep_k<<<dim3(8,5),256>>>(qw, vw, pww, o1w, o2w);
    conv1x1_mma_k<<<dim3(HWSZ/128, BB),    256>>>(query,  p_wprep + 0*8*4096, qb,  p_q,   0, 0, nullptr);
    conv1x1_mma_k<<<dim3(HWSZ/128, BB*NN), 256>>>(values, p_wprep + 1*8*4096, vb,  p_v,   0, 0, nullptr);
    dw_k<<<dim3(3,3,BB*CCH), 256>>>(query, dww, dwb);
    conv1x1_mma_k<<<dim3(HWSZ/128, BB),    256>>>(p_tmp,  p_wprep + 2*8*4096, pwb, p_net, 0, 1, nullptr);
    fused_k<<<(BB*HEADS*HWSZ)/128, 128>>>(wih, whh, bih, bhh, offw, offb, aw, ab);
    conv1x1_mma_k<<<dim3(HWSZ/128, BB),    256>>>(p_agg,  p_wprep + 3*8*4096, o1b, p_tmp, 1, 0, nullptr);
    conv1x1_mma_k<<<dim3(HWSZ/128, BB),    256>>>(p_tmp,  p_wprep + 4*8*4096, o2b, out,   2, 0, gate);
    ent_k<<<(BB*HWSZ)/128, 128>>>(out);
}

// round 8
// speedup vs baseline: 1.5394x; 1.0325x over previous
#include <cuda_runtime.h>
#include <math.h>
#include <stdint.h>

#define BB 2
#define NN 4
#define CCH 128
#define HEADS 8
#define PP 4
#define HH 96
#define WW 96
#define TCC 64
#define NITERS 3
#define HD 16
#define HWSZ (HH*WW)   // 9216
#define BPITCH 40

// ---------------- scratch (device globals; no allocation) ----------------
__device__ float g_q   [BB*CCH*HWSZ];          // BCHW
__device__ float g_v   [BB*NN*CCH*HWSZ];       // BCHW
__device__ float g_tmp [BB*CCH*HWSZ];          // BCHW
__device__ float g_net [BB*HEADS*HWSZ*HD];     // pixel-head-major
__device__ float g_agg [BB*CCH*HWSZ];          // BCHW
__device__ float g_ent [BB*HEADS*HWSZ];
__device__ float g_tbias[BB*HEADS*NN];
__device__ int   g_nid [BB];
__device__ float g_wprep[5*8*4096];            // pre-split/permuted conv weights

__device__ __forceinline__ float geluf(float v){ return 0.5f*v*(1.0f+erff(v*0.70710678118654752f)); }
__device__ __forceinline__ float sigm(float v){ return 1.0f/(1.0f+expf(-v)); }
__device__ __forceinline__ float tf32r(float x){
    uint32_t o; asm("cvt.rna.tf32.f32 %0, %1;" : "=r"(o) : "f"(x));
    return __uint_as_float(o);
}
__device__ __forceinline__ void mma8(float* c, const float* a, const float* b){
    asm volatile("mma.sync.aligned.m16n8k8.row.col.f32.tf32.tf32.f32 "
        "{%0,%1,%2,%3}, {%4,%5,%6,%7}, {%8,%9}, {%0,%1,%2,%3};"
        : "+f"(c[0]),"+f"(c[1]),"+f"(c[2]),"+f"(c[3])
        : "r"(__float_as_uint(a[0])),"r"(__float_as_uint(a[1])),
          "r"(__float_as_uint(a[2])),"r"(__float_as_uint(a[3])),
          "r"(__float_as_uint(b[0])),"r"(__float_as_uint(b[1])));
}

// ---------------- weight prep: permute + hi/lo split, once ----------------
__global__ void wprep_k(const float* __restrict__ qw, const float* __restrict__ vw,
                        const float* __restrict__ pww, const float* __restrict__ o1w,
                        const float* __restrict__ o2w)
{
    const float* ws[5] = {qw, vw, pww, o1w, o2w};
    int ck = blockIdx.x;            // k-chunk 0..7
    int ci = blockIdx.y;            // conv id 0..4
    const float* w = ws[ci];
    int tid = threadIdx.x;
    int oc  = tid >> 1;
    int klb = (tid & 1) * 8;
    const float* wp = w + (size_t)oc * CCH + ck*16 + klb;
    float4 v0 = *reinterpret_cast<const float4*>(wp);
    float4 v1 = *reinterpret_cast<const float4*>(wp + 4);
    float vv[8] = {v0.x,v0.y,v0.z,v0.w,v1.x,v1.y,v1.z,v1.w};
    int mt = oc >> 4, og = oc & 15, gi = og & 7, half = og >> 3;
    float* dst = g_wprep + ((size_t)ci*8 + ck)*4096;
    #pragma unroll
    for (int j=0;j<8;j++){
        int kl = klb + j;
        int kc = kl >> 3, kk = kl & 7;
        int tt = kk & 3, khalf = kk >> 2;
        int idx = ((mt*2+kc)*32 + gi*4 + tt)*4 + (half + 2*khalf);
        float hi = tf32r(vv[j]);
        dst[idx]        = hi;
        dst[2048 + idx] = tf32r(vv[j] - hi);
    }
}

// ---------------- tiny kernel: t_bias + nearest_idx ----------------
__global__ void small_k(const float* __restrict__ rel_time,
                        const float* __restrict__ time_enc,
                        const float* __restrict__ tw,
                        const float* __restrict__ tb)
{
    int t = threadIdx.x;
    if (t < BB*HEADS*NN) {
        int n = t % NN; int h = (t/NN) % HEADS; int b = t/(NN*HEADS);
        float s = tb[h];
        for (int k=0;k<TCC;k++) s += time_enc[(b*NN+n)*TCC+k]*tw[h*TCC+k];
        g_tbias[t] = s;
    } else if (t < BB*HEADS*NN + BB) {
        int b = t - BB*HEADS*NN;
        float best = fabsf(rel_time[b*NN]); int id = 0;
        for (int n=1;n<NN;n++){ float v=fabsf(rel_time[b*NN+n]); if (v<best){best=v;id=n;} }
        g_nid[b] = id;
    }
}

// ---------------- depthwise 7x7 + bias + gelu (smem tiled) ----------------
__global__ __launch_bounds__(256)
void dw_k(const float* __restrict__ q,
          const float* __restrict__ dww,
          const float* __restrict__ dwb)
{
    __shared__ float tile[38][40];
    __shared__ float wsm[49];
    int plane = blockIdx.z;            // b*CCH + c
    int c = plane & (CCH-1);
    int tx0 = blockIdx.x * 32;
    int ty0 = blockIdx.y * 32;
    const float* qp = q + (size_t)plane * HWSZ;
    int tid = threadIdx.x;
    if (tid < 49) wsm[tid] = dww[c*49 + tid];
    for (int i = tid; i < 38*38; i += 256){
        int r = i / 38, cc = i - r*38;
        int gy = ty0 + r - 3, gx = tx0 + cc - 3;
        float v = 0.f;
        if (gy>=0 && gy<HH && gx>=0 && gx<WW) v = qp[gy*WW+gx];
        tile[r][cc] = v;
    }
    __syncthreads();
    float wr[49];
    #pragma unroll
    for (int i=0;i<49;i++) wr[i]=wsm[i];
    int lx = tid & 31;
    int ly0 = tid >> 5;
    float bz = dwb[c];
    float* outp = g_tmp + (size_t)plane*HWSZ;
    #pragma unroll
    for (int j=0;j<4;j++){
        int ly = ly0 + j*8;
        float acc = 0.f;
        #pragma unroll
        for (int ky=0;ky<7;ky++)
            #pragma unroll
            for (int kx=0;kx<7;kx++)
                acc += tile[ly+ky][lx+kx]*wr[ky*7+kx];
        outp[(ty0+ly)*WW + tx0+lx] = geluf(acc + bz);
    }
}

// ---------------- 3xTF32 tensor-core conv1x1 (fp32-accurate) ----------------
__global__ __launch_bounds__(256, 2)
void conv1x1_mma_k(const float* __restrict__ in, const float* __restrict__ wA,
                   const float* __restrict__ bias, float* __restrict__ out,
                   int act, int layout, const float* __restrict__ gate)
{
    __shared__ float sA[4096];           // [hi2048 | lo2048] permuted W chunk
    __shared__ float sB[2][16*132];      // hi/lo [k16][pix128 + pad4]
    const int tid  = threadIdx.x;
    const int lane = tid & 31;
    const int warp = tid >> 5;
    const int g  = lane >> 2;
    const int t4 = lane & 3;

    const int pix0 = blockIdx.x * 128;
    const int img  = blockIdx.y;
    const float* inb = in + (size_t)img * CCH * HWSZ;

    const int wOc  = (warp & 1) * 64;
    const int wPix = (warp >> 1) * 32;

    float c[4][4][4];
    #pragma unroll
    for (int i=0;i<4;i++)
        #pragma unroll
        for (int j=0;j<4;j++)
            #pragma unroll
            for (int r=0;r<4;r++) c[i][j][r]=0.f;

    for (int k0 = 0; k0 < CCH; k0 += 16) {
        {
            const float4* src = reinterpret_cast<const float4*>(wA + (size_t)(k0>>4)*4096);
            float4* dA = reinterpret_cast<float4*>(sA);
            dA[tid]       = src[tid];
            dA[tid + 256] = src[tid + 256];
            dA[tid + 512] = src[tid + 512];
            dA[tid + 768] = src[tid + 768];
        }
        {
            int kl = tid >> 4;
            int px = (tid & 15) * 8;
            const float* ip = inb + (size_t)(k0+kl)*HWSZ + pix0 + px;
            float4 v0 = *reinterpret_cast<const float4*>(ip);
            float4 v1 = *reinterpret_cast<const float4*>(ip+4);
            float vv[8] = {v0.x,v0.y,v0.z,v0.w,v1.x,v1.y,v1.z,v1.w};
            int base = kl*132 + px;
            #pragma unroll
            for (int j=0;j<8;j++){
                float hi = tf32r(vv[j]);
                sB[0][base+j] = hi;
                sB[1][base+j] = tf32r(vv[j] - hi);
            }
        }
        __syncthreads();
        #pragma unroll
        for (int kc=0; kc<2; kc++){
            float ah[4][4], al[4][4];
            #pragma unroll
            for (int mt=0; mt<4; mt++){
                int mtg = (wOc>>4) + mt;
                int idx = ((mtg*2+kc)*32+lane)*4;
                float4 avh = *reinterpret_cast<const float4*>(&sA[idx]);
                float4 avl = *reinterpret_cast<const float4*>(&sA[2048+idx]);
                ah[mt][0]=avh.x; ah[mt][1]=avh.y; ah[mt][2]=avh.z; ah[mt][3]=avh.w;
                al[mt][0]=avl.x; al[mt][1]=avl.y; al[mt][2]=avl.z; al[mt][3]=avl.w;
            }
            float bh[4][2], bl[4][2];
            #pragma unroll
            for (int nt=0; nt<4; nt++){
                int px = wPix + nt*8 + g;
                int i0 = (kc*8+t4)*132 + px;
                int i1 = (kc*8+t4+4)*132 + px;
                bh[nt][0] = sB[0][i0];  bh[nt][1] = sB[0][i1];
                bl[nt][0] = sB[1][i0];  bl[nt][1] = sB[1][i1];
            }
            #pragma unroll
            for (int mt=0; mt<4; mt++)
                #pragma unroll
                for (int nt=0; nt<4; nt++){
                    mma8(c[mt][nt], ah[mt], bl[nt]);
                    mma8(c[mt][nt], al[mt], bh[nt]);
                    mma8(c[mt][nt], ah[mt], bh[nt]);
                }
        }
        __syncthreads();
    }

    #pragma unroll
    for (int mt=0; mt<4; mt++){
        int oc1 = wOc + mt*16 + g;
        int oc2 = oc1 + 8;
        float b1 = bias[oc1], b2 = bias[oc2];
        float m1 = 1.f, m2 = 1.f;
        if (act==2){ m1 = sigm(gate[oc1]); m2 = sigm(gate[oc2]); }
        #pragma unroll
        for (int nt=0; nt<4; nt++){
            int p = pix0 + wPix + nt*8 + t4*2;
            float v0 = c[mt][nt][0] + b1, v1 = c[mt][nt][1] + b1;
            float v2 = c[mt][nt][2] + b2, v3 = c[mt][nt][3] + b2;
            if (act==1){ v0=geluf(v0); v1=geluf(v1); v2=geluf(v2); v3=geluf(v3); }
            else if (act==2){ v0*=m1; v1*=m1; v2*=m2; v3*=m2; }
            if (layout==0){
                float2* o1 = reinterpret_cast<float2*>(out + (size_t)img*CCH*HWSZ + (size_t)oc1*HWSZ + p);
                float2* o2 = reinterpret_cast<float2*>(out + (size_t)img*CCH*HWSZ + (size_t)oc2*HWSZ + p);
                *o1 = make_float2(v0, v1);
                *o2 = make_float2(v2, v3);
            } else {
                out[(((size_t)img*HEADS + (oc1>>4))*HWSZ + p  )*HD + (oc1&15)] = v0;
                out[(((size_t)img*HEADS + (oc1>>4))*HWSZ + p+1)*HD + (oc1&15)] = v1;
                out[(((size_t)img*HEADS + (oc2>>4))*HWSZ + p  )*HD + (oc2&15)] = v2;
                out[(((size_t)img*HEADS + (oc2>>4))*HWSZ + p+1)*HD + (oc2&15)] = v3;
            }
        }
    }
}

// ---------------- fused: correlation + MMA-GRU + softmax + final gather ----------------
// dyn smem layout (floats):
//   0     s_wih 864      | 864  s_whh 768   | 1632 s_bsum 32 | 1664 s_bihn 16
//   1680  s_bhhn 16      | 1696 s_offw 128  | 1824 s_aw 64   | 1888 s_offb 8 | 1896 s_ab 4 (+4 pad)
//   1904  aF_h 1920      | 3824 aF_l 1920
//   5744  s_bh 4*1600    | 12144 s_bl 4*1600 | 18544 s_n 4*640   → total 21104
#define FK_SMEM_FLOATS 21104
__global__ __launch_bounds__(128)
void fused_k(const float* __restrict__ wih, const float* __restrict__ whh,
             const float* __restrict__ bih, const float* __restrict__ bhh,
             const float* __restrict__ offw, const float* __restrict__ offb,
             const float* __restrict__ aw,  const float* __restrict__ ab)
{
    extern __shared__ float sm[];
    float* s_wih = sm;
    float* s_whh = sm+864;
    float* s_bsum= sm+1632;
    float* s_bihn= sm+1664;
    float* s_bhhn= sm+1680;
    float* s_offw= sm+1696;
    float* s_aw  = sm+1824;
    float* s_offb= sm+1888;
    float* s_ab  = sm+1896;
    float* aF_h  = sm+1904;
    float* aF_l  = sm+3824;
    float* s_bhA = sm+5744;
    float* s_blA = sm+12144;
    float* s_nA  = sm+18544;

    int t = threadIdx.x;
    int lane = t & 31, warp = t >> 5;
    int g = lane >> 2, t4 = lane & 3;

    for (int i=t;i<864;i+=128) s_wih[i]=wih[i];
    for (int i=t;i<768;i+=128) s_whh[i]=whh[i];
    if (t<32) s_bsum[t]=bih[t]+bhh[t];
    else if (t<48){ s_bihn[t-32]=bih[t]; s_bhhn[t-32]=bhh[t]; }
    s_offw[t] = offw[t];
    if (t<64) s_aw[t] = aw[t];
    if (t>=64 && t<72) s_offb[t-64]=offb[t-64];
    if (t>=72 && t<76) s_ab[t-72]=ab[t-72];
    __syncthreads();

    // ---- prep GRU weight A-fragments (tiles: tt = kt*3+mt, kt 0..4, mt 0..2) ----
    for (int tt=warp; tt<15; tt+=4){
        int kt = tt/3, mt = tt - kt*3;
        #pragma unroll
        for (int idx=0; idx<4; idx++){
            int row = g + ((idx & 1) << 3);           // A-frag: idx1,3 -> +8 row
            int col = kt*8 + t4 + ((idx >> 1) << 2);  // idx2,3 -> +4 col
            float e;
            if (mt < 2){
                int j = mt*16 + row;
                e = (col < 18) ? s_wih[j*18+col] : ((col < 24) ? 0.f : s_whh[j*16 + col-24]);
            } else if (kt < 3){
                e = (col < 18) ? s_wih[(32+row)*18 + col] : 0.f;
            } else {
                e = s_whh[(32+row)*16 + (col-24)];
            }
            float h = tf32r(e);
            aF_h[(tt*32+lane)*4+idx] = h;
            aF_l[(tt*32+lane)*4+idx] = tf32r(e - h);
        }
    }

    float* bhb = s_bhA + warp*1600;
    float* blb = s_blA + warp*1600;
    float* s_nw = s_nA + warp*640;
    // zero B rows 18..23
    for (int i=lane; i<6*BPITCH; i+=32){ bhb[18*BPITCH+i]=0.f; blb[18*BPITCH+i]=0.f; }
    __syncthreads();

    int ph  = blockIdx.x*128 + t;
    int pix = ph % HWSZ;
    int bh_ = ph / HWSZ;
    int h   = bh_ % HEADS;
    int b   = bh_ / HEADS;
    int x   = pix % WW, y = pix / WW;
    float bx = -1.f + x*(2.f/(WW-1));
    float by = -1.f + y*(2.f/(HH-1));

    const float* vnear = g_v + ((size_t)(b*NN + g_nid[b])*CCH + h*HD)*HWSZ;
    const float* qbase = g_q + ((size_t)b*CCH + h*HD)*HWSZ + pix;

    // ---- correlation argmax (unchanged) ----
    float qv[HD];
    #pragma unroll
    for (int d=0;d<HD;d++) qv[d] = qbase[(size_t)d*HWSZ];
    const int sdx[5] = {0,-1,1,0,0};
    const int sdy[5] = {0,0,0,-1,1};
    float bestsc = 0.f; int bi = 0;
    #pragma unroll
    for (int s=0;s<5;s++){
        int sy = y - sdy[s], sx = x - sdx[s];
        float sc = 0.f;
        if (sy>=0 && sy<HH && sx>=0 && sx<WW){
            int sp = sy*WW+sx;
            #pragma unroll
            for (int d=0;d<HD;d++) sc += qv[d]*vnear[(size_t)d*HWSZ + sp];
        }
        if (s==0 || sc > bestsc){ bestsc = sc; bi = s; }
    }
    float ox0 = sdy[bi]*(2.f/WW);
    float oy0 = sdx[bi]*(2.f/HH);

    float offs[PP*2];
    #pragma unroll
    for (int p=0;p<PP;p++){ offs[2*p]=ox0; offs[2*p+1]=oy0; }
    float attn[PP] = {0.f,0.f,0.f,0.f};

    // ---- initial net: per-lane load, stage to s_n (fp32) + B rows 24..39 (hi/lo) ----
    {
        const float4* np4 = reinterpret_cast<const float4*>(g_net + (size_t)ph*HD);
        #pragma unroll
        for (int d4=0; d4<4; d4++){
            float4 v = np4[d4];
            float vv[4] = {v.x,v.y,v.z,v.w};
            #pragma unroll
            for (int j=0;j<4;j++){
                int d = d4*4+j;
                s_nw[d*BPITCH+lane] = vv[j];
                float hh = tf32r(vv[j]);
                bhb[(24+d)*BPITCH+lane] = hh;
                blb[(24+d)*BPITCH+lane] = tf32r(vv[j]-hh);
            }
        }
    }
    __syncwarp();
    // net in C-fragment layout regs
    float net_c[4][4];
    #pragma unroll
    for (int nt=0; nt<4; nt++)
        #pragma unroll
        for (int idx=0; idx<4; idx++){
            int row = g + ((idx>>1)<<3);          // C-frag: idx2,3 -> +8 row
            int col = nt*8 + 2*t4 + (idx&1);
            net_c[nt][idx] = s_nw[row*BPITCH+col];
        }

    // ---- 3 GRU iterations (MMA) ----
    for (int it=0; it<NITERS; it++){
        // bilinear sample at p0 (per-lane, unchanged math)
        float p0x = offs[0], p0y = offs[1];
        float sgx = fminf(fmaxf(bx+p0x,-1.f),1.f);
        float sgy = fminf(fmaxf(by+p0y,-1.f),1.f);
        float ixf = (sgx+1.f)*0.5f*(WW-1);
        float iyf = (sgy+1.f)*0.5f*(HH-1);
        float x0f = floorf(ixf), y0f = floorf(iyf);
        float wx = ixf-x0f, wy = iyf-y0f;
        int x0 = min(max((int)x0f,0),WW-1);
        int x1 = min(max((int)x0f+1,0),WW-1);
        int y0 = min(max((int)y0f,0),HH-1);
        int y1 = min(max((int)y0f+1,0),HH-1);
        int i00=y0*WW+x0, i01=y0*WW+x1, i10=y1*WW+x0, i11=y1*WW+x1;
        float w00=(1.f-wx)*(1.f-wy), w01=wx*(1.f-wy), w10=(1.f-wx)*wy, w11=wx*wy;

        float xin[HD+2];
        #pragma unroll
        for (int d=0;d<HD;d++){
            const float* pl = vnear + (size_t)d*HWSZ;
            xin[d] = pl[i00]*w00 + pl[i01]*w01 + pl[i10]*w10 + pl[i11]*w11;
        }
        xin[HD]=p0x; xin[HD+1]=p0y;

        // stage xin into B rows 0..17 (hi/lo)
        #pragma unroll
        for (int k=0;k<HD+2;k++){
            float hh = tf32r(xin[k]);
            bhb[k*BPITCH+lane] = hh;
            blb[k*BPITCH+lane] = tf32r(xin[k]-hh);
        }
        __syncwarp();

        // MMA: crz = [Wr;Wz](32x40) @ B(40x32); cgi = Wih_n @ B[0:24]; cgh = Whh_n @ B[24:40]
        float crz[2][4][4], cgi[4][4], cgh[4][4];
        #pragma unroll
        for (int mt=0;mt<2;mt++)
            #pragma unroll
            for (int nt=0;nt<4;nt++)
                #pragma unroll
                for (int r2=0;r2<4;r2++) crz[mt][nt][r2]=0.f;
        #pragma unroll
        for (int nt=0;nt<4;nt++)
            #pragma unroll
            for (int r2=0;r2<4;r2++){ cgi[nt][r2]=0.f; cgh[nt][r2]=0.f; }

        #pragma unroll
        for (int kt=0; kt<5; kt++){
            float ah[3][4], al[3][4];
            #pragma unroll
            for (int mt=0; mt<3; mt++){
                int tt = kt*3+mt;
                float4 vh = *reinterpret_cast<const float4*>(&aF_h[(tt*32+lane)*4]);
                float4 vl = *reinterpret_cast<const float4*>(&aF_l[(tt*32+lane)*4]);
                ah[mt][0]=vh.x; ah[mt][1]=vh.y; ah[mt][2]=vh.z; ah[mt][3]=vh.w;
                al[mt][0]=vl.x; al[mt][1]=vl.y; al[mt][2]=vl.z; al[mt][3]=vl.w;
            }
            float bhf[4][2], blf[4][2];
            #pragma unroll
            for (int nt=0; nt<4; nt++){
                int c0 = (kt*8+t4)*BPITCH + nt*8 + g;
                int c1 = (kt*8+t4+4)*BPITCH + nt*8 + g;
                bhf[nt][0]=bhb[c0]; bhf[nt][1]=bhb[c1];
                blf[nt][0]=blb[c0]; blf[nt][1]=blb[c1];
            }
            #pragma unroll
            for (int nt=0; nt<4; nt++){
                mma8(crz[0][nt], ah[0], blf[nt]); mma8(crz[0][nt], al[0], bhf[nt]); mma8(crz[0][nt], ah[0], bhf[nt]);
                mma8(crz[1][nt], ah[1], blf[nt]); mma8(crz[1][nt], al[1], bhf[nt]); mma8(crz[1][nt], ah[1], bhf[nt]);
                if (kt < 3){
                    mma8(cgi[nt], ah[2], blf[nt]); mma8(cgi[nt], al[2], bhf[nt]); mma8(cgi[nt], ah[2], bhf[nt]);
                } else {
                    mma8(cgh[nt], ah[2], blf[nt]); mma8(cgh[nt], al[2], bhf[nt]); mma8(cgh[nt], ah[2], bhf[nt]);
                }
            }
        }

        // elementwise GRU update in C-fragment layout
        #pragma unroll
        for (int nt=0; nt<4; nt++)
            #pragma unroll
            for (int idx=0; idx<4; idx++){
                int row = g + ((idx>>1)<<3);
                float rv = sigm(crz[0][nt][idx] + s_bsum[row]);
                float zv = sigm(crz[1][nt][idx] + s_bsum[16+row]);
                float hv = tanhf(cgi[nt][idx] + s_bihn[row] + rv*(cgh[nt][idx] + s_bhhn[row]));
                net_c[nt][idx] = (1.f-zv)*hv + zv*net_c[nt][idx];
            }
        __syncwarp();
        // store net' (fp32 to s_n; hi/lo to B rows 24..39)
        #pragma unroll
        for (int nt=0; nt<4; nt++)
            #pragma unroll
            for (int idx=0; idx<4; idx++){
                int row = g + ((idx>>1)<<3);
                int col = nt*8 + 2*t4 + (idx&1);
                float v = net_c[nt][idx];
                s_nw[row*BPITCH+col] = v;
                float hh = tf32r(v);
                bhb[(24+row)*BPITCH+col] = hh;
                blb[(24+row)*BPITCH+col] = tf32r(v-hh);
            }
        __syncwarp();

        // per-lane head matvecs using own pixel's net'
        float nloc[HD];
        #pragma unroll
        for (int d=0;d<HD;d++) nloc[d] = s_nw[d*BPITCH+lane];
        #pragma unroll
        for (int p=0;p<PP;p++){
            float d0 = s_offb[2*p], d1 = s_offb[2*p+1], da = s_ab[p];
            #pragma unroll
            for (int d=0;d<HD;d++){
                d0 += nloc[d]*s_offw[(2*p)*HD+d];
                d1 += nloc[d]*s_offw[(2*p+1)*HD+d];
                da += nloc[d]*s_aw[p*HD+d];
            }
            offs[2*p]+=d0; offs[2*p+1]+=d1; attn[p]+=da;
        }
    }

    // ---- softmax over N*P + entropy (per-lane, weights in regs) ----
    float lg[NN*PP];
    float m = -1e30f;
    #pragma unroll
    for (int n=0;n<NN;n++){
        float tbv = g_tbias[bh_*NN+n];
        #pragma unroll
        for (int p=0;p<PP;p++){ float v2 = attn[p]+tbv; lg[n*PP+p]=v2; m = fmaxf(m,v2); }
    }
    float ssum = 0.f;
    #pragma unroll
    for (int i=0;i<NN*PP;i++){ lg[i]=expf(lg[i]-m); ssum += lg[i]; }
    float inv = 1.f/ssum;
    float ent = 0.f;
    #pragma unroll
    for (int i=0;i<NN*PP;i++){ lg[i]*=inv; ent -= lg[i]*logf(lg[i]+1e-8f); }
    g_ent[(size_t)bh_*HWSZ + pix] = ent;

    // ---- final weighted gather (per-lane, unchanged) ----
    float acc[HD];
    #pragma unroll
    for (int d=0;d<HD;d++) acc[d]=0.f;
    #pragma unroll
    for (int p=0;p<PP;p++){
        float sgx = fminf(fmaxf(bx+offs[2*p],-1.f),1.f);
        float sgy = fminf(fmaxf(by+offs[2*p+1],-1.f),1.f);
        float ixf = (sgx+1.f)*0.5f*(WW-1);
        float iyf = (sgy+1.f)*0.5f*(HH-1);
        float x0f = floorf(ixf), y0f = floorf(iyf);
        float wx = ixf-x0f, wy = iyf-y0f;
        int x0 = min(max((int)x0f,0),WW-1);
        int x1 = min(max((int)x0f+1,0),WW-1);
        int y0 = min(max((int)y0f,0),HH-1);
        int y1 = min(max((int)y0f+1,0),HH-1);
        int i00=y0*WW+x0, i01=y0*WW+x1, i10=y1*WW+x0, i11=y1*WW+x1;
        float w00=(1.f-wx)*(1.f-wy), w01=wx*(1.f-wy), w10=(1.f-wx)*wy, w11=wx*wy;
        #pragma unroll
        for (int n=0;n<NN;n++){
            float wnp = lg[n*PP+p];
            const float* vb2 = g_v + ((size_t)(b*NN+n)*CCH + h*HD)*HWSZ;
            #pragma unroll
            for (int d=0;d<HD;d++){
                const float* pl = vb2 + (size_t)d*HWSZ;
                acc[d] += wnp*(pl[i00]*w00 + pl[i01]*w01 + pl[i10]*w10 + pl[i11]*w11);
            }
        }
    }
    float* op = g_agg + ((size_t)b*CCH + h*HD)*HWSZ + pix;
    #pragma unroll
    for (int d=0;d<HD;d++) op[(size_t)d*HWSZ] = acc[d];
}

// ---------------- entropy mean + confidence ----------------
__global__ void ent_k(float* __restrict__ out)
{
    int i = blockIdx.x*blockDim.x + threadIdx.x;
    if (i >= BB*HWSZ) return;
    int b = i / HWSZ, pix = i % HWSZ;
    float s = 0.f;
    #pragma unroll
    for (int h=0;h<HEADS;h++) s += g_ent[(size_t)(b*HEADS+h)*HWSZ + pix];
    s *= (1.0f/HEADS);
    float conf = 1.f - fminf(fmaxf(s/(2.7725887222397811f+1e-8f),0.f),1.f);
    out[(size_t)BB*CCH*HWSZ + i] = conf;
    out[(size_t)BB*CCH*HWSZ + BB*HWSZ + i] = s;
}

// ---------------- launch ----------------
extern "C" void kernel_launch(void* const* d_in, const int* in_sizes, int n_in,
                              void* d_out, int out_size)
{
    const float* query    = (const float*)d_in[0];
    const float* values   = (const float*)d_in[1];
    const float* rel_time = (const float*)d_in[2];
    const float* time_enc = (const float*)d_in[3];
    const float* qw  = (const float*)d_in[4];
    const float* qb  = (const float*)d_in[5];
    const float* vw  = (const float*)d_in[6];
    const float* vb  = (const float*)d_in[7];
    const float* dww = (const float*)d_in[8];
    const float* dwb = (const float*)d_in[9];
    const float* pww = (const float*)d_in[10];
    const float* pwb = (const float*)d_in[11];
    const float* wih = (const float*)d_in[12];
    const float* whh = (const float*)d_in[13];
    const float* bih = (const float*)d_in[14];
    const float* bhh = (const float*)d_in[15];
    const float* offw= (const float*)d_in[16];
    const float* offb= (const float*)d_in[17];
    const float* aw  = (const float*)d_in[18];
    const float* ab  = (const float*)d_in[19];
    const float* tw  = (const float*)d_in[20];
    const float* tb  = (const float*)d_in[21];
    const float* o1w = (const float*)d_in[22];
    const float* o1b = (const float*)d_in[23];
    const float* o2w = (const float*)d_in[24];
    const float* o2b = (const float*)d_in[25];
    const float* gate= (const float*)d_in[26];
    float* out = (float*)d_out;

    float *p_q, *p_v, *p_tmp, *p_net, *p_agg, *p_wprep;
    cudaGetSymbolAddress((void**)&p_q,    g_q);
    cudaGetSymbolAddress((void**)&p_v,    g_v);
    cudaGetSymbolAddress((void**)&p_tmp,  g_tmp);
    cudaGetSymbolAddress((void**)&p_net,  g_net);
    cudaGetSymbolAddress((void**)&p_agg,  g_agg);
    cudaGetSymbolAddress((void**)&p_wprep,g_wprep);

    static int fk_attr_set = 0;
    if (!fk_attr_set){
        cudaFuncSetAttribute(fused_k, cudaFuncAttributeMaxDynamicSharedMemorySize,
                             FK_SMEM_FLOATS*4);
        fk_attr_set = 1;
    }

    small_k<<<1,128>>>(rel_time, time_enc, tw, tb);
    wprep_k<<<dim3(8,5),256>>>(qw, vw, pww, o1w, o2w);
    conv1x1_mma_k<<<dim3(HWSZ/128, BB),    256>>>(query,  p_wprep + 0*8*4096, qb,  p_q,   0, 0, nullptr);
    conv1x1_mma_k<<<dim3(HWSZ/128, BB*NN), 256>>>(values, p_wprep + 1*8*4096, vb,  p_v,   0, 0, nullptr);
    dw_k<<<dim3(3,3,BB*CCH), 256>>>(query, dww, dwb);
    conv1x1_mma_k<<<dim3(HWSZ/128, BB),    256>>>(p_tmp,  p_wprep + 2*8*4096, pwb, p_net, 0, 1, nullptr);
    fused_k<<<(BB*HEADS*HWSZ)/128, 128, FK_SMEM_FLOATS*4>>>(wih, whh, bih, bhh, offw, offb, aw, ab);
    conv1x1_mma_k<<<dim3(HWSZ/128, BB),    256>>>(p_agg,  p_wprep + 3*8*4096, o1b, p_tmp, 1, 0, nullptr);
    conv1x1_mma_k<<<dim3(HWSZ/128, BB),    256>>>(p_tmp,  p_wprep + 4*8*4096, o2b, out,   2, 0, gate);
    ent_k<<<(BB*HWSZ)/128, 128>>>(out);
}